// round 3
// baseline (speedup 1.0000x reference)
#include <cuda_runtime.h>

// Problem constants
#define BD   2
#define SEQ  2048
#define DIM  1024
#define NH   16
#define DHD  64
#define MTOT (BD * SEQ)   // 4096 tokens

// Scratch for Q/K/V in head-major layout [B, H, S, Dh] (fp32). 16 MB each.
__device__ float g_q[BD * NH * SEQ * DHD];
__device__ float g_k[BD * NH * SEQ * DHD];
__device__ float g_v[BD * NH * SEQ * DHD];

// ---------------------------------------------------------------------------
// Kernel 1: QKV projection.  out = x @ W + b, written head-major.
// Tiled SGEMM: BM=64, BN=64, BK=16, 256 threads, 4x4 microtile per thread.
// gridDim.z = 3 selects (Wq,bq)->g_q, (Wk,bk)->g_k, (Wv,bv)->g_v.
// ---------------------------------------------------------------------------
__global__ __launch_bounds__(256)
void qkv_gemm_kernel(const float* __restrict__ x,
                     const float* __restrict__ Wq, const float* __restrict__ bq,
                     const float* __restrict__ Wk, const float* __restrict__ bk,
                     const float* __restrict__ Wv, const float* __restrict__ bv)
{
    __shared__ float As[64][17];   // [m][k], pad 17 to kill store conflicts
    __shared__ float Bs[16][68];   // [k][n], pad 68 keeps float4 alignment

    const int which = blockIdx.z;
    const float* __restrict__ W    = (which == 0) ? Wq : (which == 1) ? Wk : Wv;
    const float* __restrict__ bias = (which == 0) ? bq : (which == 1) ? bk : bv;
    float* __restrict__ dst        = (which == 0) ? g_q : (which == 1) ? g_k : g_v;

    const int m0  = blockIdx.y * 64;
    const int n0  = blockIdx.x * 64;
    const int tid = threadIdx.x;
    const int tx  = tid & 15;
    const int ty  = tid >> 4;

    // Load-index decomposition
    const int a_m = tid >> 4;   // 0..15, rows a_m + 16*j
    const int a_k = tid & 15;   // k within tile (coalesced 64B groups)
    const int b_n = tid & 63;   // n within tile (fully coalesced)
    const int b_k = tid >> 6;   // 0..3, rows b_k + 4*j

    float acc[4][4] = {};

    for (int k0 = 0; k0 < DIM; k0 += 16) {
#pragma unroll
        for (int j = 0; j < 4; j++) {
            const int row = a_m + 16 * j;
            As[row][a_k] = x[(m0 + row) * DIM + (k0 + a_k)];
        }
#pragma unroll
        for (int j = 0; j < 4; j++) {
            const int kk = b_k + 4 * j;
            Bs[kk][b_n] = W[(k0 + kk) * DIM + (n0 + b_n)];
        }
        __syncthreads();

#pragma unroll
        for (int kk = 0; kk < 16; kk++) {
            const float4 b4 = *(const float4*)&Bs[kk][tx * 4];
#pragma unroll
            for (int i = 0; i < 4; i++) {
                const float a = As[ty * 4 + i][kk];   // broadcast within warp
                acc[i][0] = fmaf(a, b4.x, acc[i][0]);
                acc[i][1] = fmaf(a, b4.y, acc[i][1]);
                acc[i][2] = fmaf(a, b4.z, acc[i][2]);
                acc[i][3] = fmaf(a, b4.w, acc[i][3]);
            }
        }
        __syncthreads();
    }

    // Epilogue: n0 is a multiple of 64 == Dh, so the whole tile is one head.
    const float4 bb = *(const float4*)&bias[n0 + tx * 4];
    const int h = n0 >> 6;
#pragma unroll
    for (int i = 0; i < 4; i++) {
        const int m  = m0 + ty * 4 + i;
        const int bi = m >> 11;          // m / SEQ
        const int s  = m & (SEQ - 1);    // m % SEQ
        float4 o;
        o.x = acc[i][0] + bb.x;
        o.y = acc[i][1] + bb.y;
        o.z = acc[i][2] + bb.z;
        o.w = acc[i][3] + bb.w;
        *(float4*)&dst[(((bi * NH + h) * SEQ + s) * DHD) + tx * 4] = o;
    }
}

// ---------------------------------------------------------------------------
// Kernel 2: flash-style attention.
// One CTA per (b, h, 64-query tile). 256 threads, 4x4 microtiles.
// Online softmax over 32 key tiles of 64 keys. Mask is an additive key bias.
// Dynamic smem layout: Qs[64*68] | Kt[64*68] (d-major) | Vs[64*68] | Ps[64*68] | Mk[64]
// ---------------------------------------------------------------------------
__global__ __launch_bounds__(256)
void attn_kernel(const int* __restrict__ mask, float* __restrict__ out)
{
    extern __shared__ float sm[];
    float* Qs = sm;                 // [row][d]   stride 68
    float* Kt = Qs + 64 * 68;       // [d][key]   stride 68 (transposed)
    float* Vs = Kt + 64 * 68;       // [key][d]   stride 68
    float* Ps = Vs + 64 * 68;       // [row][key] stride 68
    float* Mk = Ps + 64 * 68;       // [key] additive mask bias

    const int qt = blockIdx.x;      // query tile 0..31
    const int h  = blockIdx.y;
    const int b  = blockIdx.z;

    const float* __restrict__ qbase = g_q + (((size_t)(b * NH + h)) * SEQ + qt * 64) * DHD;
    const float* __restrict__ kbase = g_k + ((size_t)(b * NH + h)) * SEQ * DHD;
    const float* __restrict__ vbase = g_v + ((size_t)(b * NH + h)) * SEQ * DHD;

    const int tid = threadIdx.x;
    const int tx  = tid & 15;
    const int ty  = tid >> 4;
    const int ld  = tid & 63;       // d index for loads (coalesced)
    const int lr0 = tid >> 6;       // 0..3 row base for loads

    // Load Q tile (rows lr0 + 4*r cover 0..63)
#pragma unroll
    for (int r = 0; r < 16; r++) {
        const int row = lr0 + 4 * r;
        Qs[row * 68 + ld] = qbase[row * DHD + ld];
    }

    float m_run[4], l_run[4], acc[4][4] = {};
#pragma unroll
    for (int i = 0; i < 4; i++) { m_run[i] = -1e30f; l_run[i] = 0.0f; }

    const float scale = 0.125f;     // 1/sqrt(64)

    for (int kt0 = 0; kt0 < SEQ; kt0 += 64) {
        __syncthreads();   // previous iter done reading Kt/Vs/Ps; Qs visible on iter 0

        // Load K (store d-major) and V (natural), plus mask bias
#pragma unroll
        for (int r = 0; r < 16; r++) {
            const int key = lr0 + 4 * r;
            const float kv = kbase[(kt0 + key) * DHD + ld];
            Kt[ld * 68 + key] = kv;
            Vs[key * 68 + ld] = vbase[(kt0 + key) * DHD + ld];
        }
        if (tid < 64)
            Mk[tid] = -10000.0f * (1.0f - (float)mask[b * SEQ + kt0 + tid]);
        __syncthreads();

        // S = Q @ K^T  (64x64, 4x4 per thread)
        float s[4][4] = {};
#pragma unroll
        for (int d = 0; d < 64; d++) {
            const float4 kb = *(const float4*)&Kt[d * 68 + tx * 4];
#pragma unroll
            for (int i = 0; i < 4; i++) {
                const float a = Qs[(ty * 4 + i) * 68 + d];
                s[i][0] = fmaf(a, kb.x, s[i][0]);
                s[i][1] = fmaf(a, kb.y, s[i][1]);
                s[i][2] = fmaf(a, kb.z, s[i][2]);
                s[i][3] = fmaf(a, kb.w, s[i][3]);
            }
        }

        // Scale + mask bias
        float mk[4];
#pragma unroll
        for (int j = 0; j < 4; j++) mk[j] = Mk[tx * 4 + j];
#pragma unroll
        for (int i = 0; i < 4; i++)
#pragma unroll
            for (int j = 0; j < 4; j++)
                s[i][j] = s[i][j] * scale + mk[j];

        // Online softmax per row (row group = 16 lanes sharing ty)
#pragma unroll
        for (int i = 0; i < 4; i++) {
            float mx = fmaxf(fmaxf(s[i][0], s[i][1]), fmaxf(s[i][2], s[i][3]));
#pragma unroll
            for (int o = 1; o < 16; o <<= 1)
                mx = fmaxf(mx, __shfl_xor_sync(0xffffffffu, mx, o));

            const float m_new = fmaxf(m_run[i], mx);
            const float fac   = __expf(m_run[i] - m_new);
            m_run[i] = m_new;

            float rs = 0.0f;
#pragma unroll
            for (int j = 0; j < 4; j++) {
                s[i][j] = __expf(s[i][j] - m_new);
                rs += s[i][j];
            }
#pragma unroll
            for (int o = 1; o < 16; o <<= 1)
                rs += __shfl_xor_sync(0xffffffffu, rs, o);

            l_run[i] = l_run[i] * fac + rs;
#pragma unroll
            for (int j = 0; j < 4; j++) acc[i][j] *= fac;

            // Stage P row segment to smem (float4, conflict-free)
            *(float4*)&Ps[(ty * 4 + i) * 68 + tx * 4] =
                make_float4(s[i][0], s[i][1], s[i][2], s[i][3]);
        }
        __syncthreads();

        // acc += P @ V  (inner over 64 keys)
#pragma unroll
        for (int j = 0; j < 64; j++) {
            const float4 vb = *(const float4*)&Vs[j * 68 + tx * 4];
#pragma unroll
            for (int i = 0; i < 4; i++) {
                const float p = Ps[(ty * 4 + i) * 68 + j];
                acc[i][0] = fmaf(p, vb.x, acc[i][0]);
                acc[i][1] = fmaf(p, vb.y, acc[i][1]);
                acc[i][2] = fmaf(p, vb.z, acc[i][2]);
                acc[i][3] = fmaf(p, vb.w, acc[i][3]);
            }
        }
    }

    // Epilogue: out[b][s][h*64 + d] = acc / l
#pragma unroll
    for (int i = 0; i < 4; i++) {
        const int srow = qt * 64 + ty * 4 + i;
        const float inv = 1.0f / l_run[i];
        float4 o;
        o.x = acc[i][0] * inv;
        o.y = acc[i][1] * inv;
        o.z = acc[i][2] * inv;
        o.w = acc[i][3] * inv;
        *(float4*)&out[((size_t)(b * SEQ + srow)) * DIM + h * DHD + tx * 4] = o;
    }
}

// ---------------------------------------------------------------------------
// Launch
// ---------------------------------------------------------------------------
extern "C" void kernel_launch(void* const* d_in, const int* in_sizes, int n_in,
                              void* d_out, int out_size)
{
    const float* x    = (const float*)d_in[0];
    const int*   mask = (const int*)  d_in[1];
    const float* Wq   = (const float*)d_in[2];
    const float* bq   = (const float*)d_in[3];
    const float* Wk   = (const float*)d_in[4];
    const float* bk   = (const float*)d_in[5];
    const float* Wv   = (const float*)d_in[6];
    const float* bv   = (const float*)d_in[7];
    float* out = (float*)d_out;

    // QKV projection: 16 n-tiles x 64 m-tiles x 3 matrices
    dim3 g1(DIM / 64, MTOT / 64, 3);
    qkv_gemm_kernel<<<g1, 256>>>(x, Wq, bq, Wk, bk, Wv, bv);

    // Attention: (q-tiles, heads, batch)
    const int smem_bytes = (4 * 64 * 68 + 64) * (int)sizeof(float);  // 69888
    cudaFuncSetAttribute(attn_kernel,
                         cudaFuncAttributeMaxDynamicSharedMemorySize, smem_bytes);
    dim3 g2(SEQ / 64, NH, BD);
    attn_kernel<<<g2, 256, smem_bytes>>>(mask, out);
}

// round 10
// speedup vs baseline: 2.5260x; 2.5260x over previous
#include <cuda_runtime.h>
#include <cuda_bf16.h>
#include <cstdint>

// Problem constants
#define BD   2
#define SEQ  2048
#define DIM  1024
#define NH   16
#define DHD  64
#define MTOT (BD * SEQ)   // 4096 tokens

// Scratch (device globals; no allocation allowed).
// x and W^T as bf16 hi/lo; Q/K/V head-major [b,h,s,dh] as bf16 hi/lo.
__device__ __nv_bfloat16 g_x_hi[MTOT * DIM];
__device__ __nv_bfloat16 g_x_lo[MTOT * DIM];
__device__ __nv_bfloat16 g_w_hi[3 * DIM * DIM];   // [which][n][k]  (W transposed)
__device__ __nv_bfloat16 g_w_lo[3 * DIM * DIM];
__device__ __nv_bfloat16 g_qh[MTOT * DIM];
__device__ __nv_bfloat16 g_ql[MTOT * DIM];
__device__ __nv_bfloat16 g_kh[MTOT * DIM];
__device__ __nv_bfloat16 g_kl[MTOT * DIM];
__device__ __nv_bfloat16 g_vh[MTOT * DIM];
__device__ __nv_bfloat16 g_vl[MTOT * DIM];

// ---------------------------------------------------------------------------
// mma.sync / ldmatrix helpers (sm_80+ features — compile on plain compute_103)
// ---------------------------------------------------------------------------
__device__ __forceinline__ uint32_t smem_u32(const void* p) {
    uint32_t a;
    asm("{ .reg .u64 t; cvta.to.shared.u64 t, %1; cvt.u32.u64 %0, t; }"
        : "=r"(a) : "l"(p));
    return a;
}

__device__ __forceinline__ void ldsm_x4(uint32_t addr, uint32_t* r) {
    asm volatile("ldmatrix.sync.aligned.m8n8.x4.shared.b16 {%0,%1,%2,%3}, [%4];"
        : "=r"(r[0]), "=r"(r[1]), "=r"(r[2]), "=r"(r[3]) : "r"(addr));
}
__device__ __forceinline__ void ldsm_x4_t(uint32_t addr, uint32_t* r) {
    asm volatile("ldmatrix.sync.aligned.m8n8.x4.trans.shared.b16 {%0,%1,%2,%3}, [%4];"
        : "=r"(r[0]), "=r"(r[1]), "=r"(r[2]), "=r"(r[3]) : "r"(addr));
}

// D(m16n8, f32) += A(m16k16, bf16) * B(k16n8, bf16)
__device__ __forceinline__ void mma16816(float* d, const uint32_t* a, const uint32_t* b) {
    asm volatile(
        "mma.sync.aligned.m16n8k16.row.col.f32.bf16.bf16.f32 "
        "{%0,%1,%2,%3}, {%4,%5,%6,%7}, {%8,%9}, {%0,%1,%2,%3};"
        : "+f"(d[0]), "+f"(d[1]), "+f"(d[2]), "+f"(d[3])
        : "r"(a[0]), "r"(a[1]), "r"(a[2]), "r"(a[3]), "r"(b[0]), "r"(b[1]));
}

__device__ __forceinline__ uint32_t pack_bf2(__nv_bfloat16 a, __nv_bfloat16 b) {
    __nv_bfloat162 t = __halves2bfloat162(a, b);
    return *reinterpret_cast<uint32_t*>(&t);
}

// ---------------------------------------------------------------------------
// Prep 1: x (fp32) -> bf16 hi/lo split
// ---------------------------------------------------------------------------
__global__ __launch_bounds__(256)
void cvt_x_kernel(const float* __restrict__ x)
{
    const int i = blockIdx.x * 256 + threadIdx.x;   // one float4 per thread
    const float4 v = ((const float4*)x)[i];
    const __nv_bfloat16 h0 = __float2bfloat16(v.x);
    const __nv_bfloat16 h1 = __float2bfloat16(v.y);
    const __nv_bfloat16 h2 = __float2bfloat16(v.z);
    const __nv_bfloat16 h3 = __float2bfloat16(v.w);
    const __nv_bfloat16 l0 = __float2bfloat16(v.x - __bfloat162float(h0));
    const __nv_bfloat16 l1 = __float2bfloat16(v.y - __bfloat162float(h1));
    const __nv_bfloat16 l2 = __float2bfloat16(v.z - __bfloat162float(h2));
    const __nv_bfloat16 l3 = __float2bfloat16(v.w - __bfloat162float(h3));
    ((__nv_bfloat162*)g_x_hi)[2 * i]     = __halves2bfloat162(h0, h1);
    ((__nv_bfloat162*)g_x_hi)[2 * i + 1] = __halves2bfloat162(h2, h3);
    ((__nv_bfloat162*)g_x_lo)[2 * i]     = __halves2bfloat162(l0, l1);
    ((__nv_bfloat162*)g_x_lo)[2 * i + 1] = __halves2bfloat162(l2, l3);
}

// ---------------------------------------------------------------------------
// Prep 2: W[k][n] (fp32) -> transposed bf16 hi/lo [n][k]
// ---------------------------------------------------------------------------
__global__ __launch_bounds__(256)
void cvt_w_kernel(const float* __restrict__ Wq, const float* __restrict__ Wk,
                  const float* __restrict__ Wv)
{
    __shared__ float t[32][33];
    const int which = blockIdx.z;
    const float* __restrict__ W = (which == 0) ? Wq : (which == 1) ? Wk : Wv;
    const int n0 = blockIdx.x * 32;
    const int k0 = blockIdx.y * 32;
    const int tx = threadIdx.x;     // 0..31
    const int ty = threadIdx.y;     // 0..7

#pragma unroll
    for (int j = 0; j < 4; j++)
        t[ty + 8 * j][tx] = W[(k0 + ty + 8 * j) * DIM + n0 + tx];
    __syncthreads();

    __nv_bfloat16* __restrict__ gh = g_w_hi + which * DIM * DIM;
    __nv_bfloat16* __restrict__ gl = g_w_lo + which * DIM * DIM;
#pragma unroll
    for (int j = 0; j < 4; j++) {
        const int n = n0 + ty + 8 * j;
        const int k = k0 + tx;
        const float w = t[tx][ty + 8 * j];       // = W[k][n]
        const __nv_bfloat16 h = __float2bfloat16(w);
        const __nv_bfloat16 l = __float2bfloat16(w - __bfloat162float(h));
        gh[n * DIM + k] = h;
        gl[n * DIM + k] = l;
    }
}

// ---------------------------------------------------------------------------
// Kernel 1: QKV projection on mma.sync bf16 (hi/lo split, 3 MMAs).
// Tile BM=128 x BN=64 (one head), BK=64. 8 warps, warp tile 32x32.
// Epilogue writes bf16 hi/lo Q/K/V in [b,h,s,dh].
// smem (bf16 elems, row stride 72): Ahi[128*72] Alo Bhi[64*72] Blo
// ---------------------------------------------------------------------------
#define PJ_AHI 0
#define PJ_ALO (128 * 72)
#define PJ_BHI (256 * 72)
#define PJ_BLO (320 * 72)
#define PJ_SMEM_BYTES (384 * 72 * 2)   // 55296

__global__ __launch_bounds__(256)
void qkv_mma_kernel(const float* __restrict__ bq, const float* __restrict__ bk,
                    const float* __restrict__ bv)
{
    extern __shared__ __nv_bfloat16 sm[];
    const int tid = threadIdx.x;
    const int l   = tid & 31;
    const int wid = tid >> 5;
    const int which = blockIdx.z;
    const int n0 = blockIdx.x * 64;
    const int m0 = blockIdx.y * 128;

    const __nv_bfloat16* __restrict__ Ah = g_x_hi + (size_t)m0 * DIM;
    const __nv_bfloat16* __restrict__ Al = g_x_lo + (size_t)m0 * DIM;
    const __nv_bfloat16* __restrict__ Bh = g_w_hi + (size_t)which * DIM * DIM + (size_t)n0 * DIM;
    const __nv_bfloat16* __restrict__ Bl = g_w_lo + (size_t)which * DIM * DIM + (size_t)n0 * DIM;

    const uint32_t sb = smem_u32(sm);
    const int mbase = (wid >> 1) * 32;
    const int nbase = (wid & 1) * 32;

    float acc[2][4][4] = {};

    for (int k0 = 0; k0 < DIM; k0 += 64) {
        __syncthreads();   // previous compute done before overwriting tiles
#pragma unroll
        for (int i = 0; i < 4; i++) {
            const int idx = i * 256 + tid;
            const int row = idx >> 3;
            const int c   = (idx & 7) * 8;
            *(uint4*)&sm[PJ_AHI + row * 72 + c] = *(const uint4*)(Ah + row * DIM + k0 + c);
            *(uint4*)&sm[PJ_ALO + row * 72 + c] = *(const uint4*)(Al + row * DIM + k0 + c);
        }
#pragma unroll
        for (int i = 0; i < 2; i++) {
            const int idx = i * 256 + tid;
            const int row = idx >> 3;
            const int c   = (idx & 7) * 8;
            *(uint4*)&sm[PJ_BHI + row * 72 + c] = *(const uint4*)(Bh + row * DIM + k0 + c);
            *(uint4*)&sm[PJ_BLO + row * 72 + c] = *(const uint4*)(Bl + row * DIM + k0 + c);
        }
        __syncthreads();

#pragma unroll
        for (int ks = 0; ks < 4; ks++) {
            uint32_t ah[2][4], al[2][4], bh[4][2], bl[4][2];
#pragma unroll
            for (int mt = 0; mt < 2; mt++) {
                const uint32_t off = (uint32_t)(mbase + mt * 16 + (l & 15)) * 72
                                   + ks * 16 + (l >> 4) * 8;
                ldsm_x4(sb + (PJ_AHI + off) * 2, ah[mt]);
                ldsm_x4(sb + (PJ_ALO + off) * 2, al[mt]);
            }
#pragma unroll
            for (int nh = 0; nh < 2; nh++) {
                const uint32_t rowB = nbase + nh * 16 + (l & 7) + (l >> 4) * 8;
                const uint32_t kB   = ks * 16 + ((l >> 3) & 1) * 8;
                const uint32_t off  = rowB * 72 + kB;
                uint32_t q[4];
                ldsm_x4(sb + (PJ_BHI + off) * 2, q);
                bh[nh * 2][0] = q[0]; bh[nh * 2][1] = q[1];
                bh[nh * 2 + 1][0] = q[2]; bh[nh * 2 + 1][1] = q[3];
                ldsm_x4(sb + (PJ_BLO + off) * 2, q);
                bl[nh * 2][0] = q[0]; bl[nh * 2][1] = q[1];
                bl[nh * 2 + 1][0] = q[2]; bl[nh * 2 + 1][1] = q[3];
            }
#pragma unroll
            for (int mt = 0; mt < 2; mt++)
#pragma unroll
                for (int nf = 0; nf < 4; nf++) {
                    mma16816(acc[mt][nf], ah[mt], bh[nf]);
                    mma16816(acc[mt][nf], ah[mt], bl[nf]);
                    mma16816(acc[mt][nf], al[mt], bh[nf]);
                }
        }
    }

    // Epilogue: bias, hi/lo split, store bf162 pairs head-major.
    const float* __restrict__ bias = (which == 0) ? bq : (which == 1) ? bk : bv;
    __nv_bfloat16* __restrict__ dsth = (which == 0) ? g_qh : (which == 1) ? g_kh : g_vh;
    __nv_bfloat16* __restrict__ dstl = (which == 0) ? g_ql : (which == 1) ? g_kl : g_vl;
    const int h = n0 >> 6;

#pragma unroll
    for (int mt = 0; mt < 2; mt++)
#pragma unroll
        for (int i = 0; i < 2; i++) {
            const int m = m0 + mbase + mt * 16 + (l >> 2) + i * 8;
            const int b = m >> 11;
            const int s = m & (SEQ - 1);
            const size_t base = ((size_t)((b * NH + h) * SEQ) + s) * DHD;
#pragma unroll
            for (int nf = 0; nf < 4; nf++) {
                const int dcol = nbase + nf * 8 + (l & 3) * 2;
                const float v0 = acc[mt][nf][i * 2]     + bias[n0 + dcol];
                const float v1 = acc[mt][nf][i * 2 + 1] + bias[n0 + dcol + 1];
                const __nv_bfloat16 h0 = __float2bfloat16(v0);
                const __nv_bfloat16 h1 = __float2bfloat16(v1);
                const __nv_bfloat16 q0 = __float2bfloat16(v0 - __bfloat162float(h0));
                const __nv_bfloat16 q1 = __float2bfloat16(v1 - __bfloat162float(h1));
                *(__nv_bfloat162*)&dsth[base + dcol] = __halves2bfloat162(h0, h1);
                *(__nv_bfloat162*)&dstl[base + dcol] = __halves2bfloat162(q0, q1);
            }
        }
}

// ---------------------------------------------------------------------------
// Kernel 2: flash attention on mma.sync bf16 (hi/lo split everywhere).
// CTA = 128 queries x (h, b). 8 warps; warp w owns rows w*16..w*16+15 and the
// FULL key range of each 64-key tile (no cross-warp softmax/PV reduction).
// P stays in registers: S C-frags repack bit-exactly into PV A-frags.
// V B-frags via ldmatrix.trans (V stored [s][dh], no transposed copy needed).
// smem (stride 72): Qh Ql [128*72] | Kh Kl Vh Vl [64*72] | Mk[64] floats
// ---------------------------------------------------------------------------
#define AT_QH 0
#define AT_QL (128 * 72)
#define AT_KH (256 * 72)
#define AT_KL (320 * 72)
#define AT_VH (384 * 72)
#define AT_VL (448 * 72)
#define AT_SMEM_BYTES (512 * 72 * 2 + 64 * 4)   // 73984

__global__ __launch_bounds__(256)
void attn_mma_kernel(const int* __restrict__ mask, float* __restrict__ out)
{
    extern __shared__ __nv_bfloat16 sm[];
    float* Mkf = (float*)(sm + 512 * 72);

    const int tid = threadIdx.x;
    const int l   = tid & 31;
    const int w   = tid >> 5;
    const int qt  = blockIdx.x;
    const int h   = blockIdx.y;
    const int b   = blockIdx.z;

    const size_t headoff = (size_t)((b * NH + h) * SEQ) * DHD;
    const __nv_bfloat16* __restrict__ Qh = g_qh + headoff + (size_t)qt * 128 * DHD;
    const __nv_bfloat16* __restrict__ Ql = g_ql + headoff + (size_t)qt * 128 * DHD;
    const __nv_bfloat16* __restrict__ Kh = g_kh + headoff;
    const __nv_bfloat16* __restrict__ Kl = g_kl + headoff;
    const __nv_bfloat16* __restrict__ Vh = g_vh + headoff;
    const __nv_bfloat16* __restrict__ Vl = g_vl + headoff;
    const uint32_t sb = smem_u32(sm);

    // Stage Q tile, then lift this warp's Q fragments into registers.
#pragma unroll
    for (int i = 0; i < 4; i++) {
        const int idx = i * 256 + tid;
        const int row = idx >> 3;
        const int c   = (idx & 7) * 8;
        *(uint4*)&sm[AT_QH + row * 72 + c] = *(const uint4*)(Qh + row * DHD + c);
        *(uint4*)&sm[AT_QL + row * 72 + c] = *(const uint4*)(Ql + row * DHD + c);
    }
    __syncthreads();

    uint32_t qfh[4][4], qfl[4][4];
#pragma unroll
    for (int ks = 0; ks < 4; ks++) {
        const uint32_t off = (uint32_t)(w * 16 + (l & 15)) * 72 + ks * 16 + (l >> 4) * 8;
        ldsm_x4(sb + (AT_QH + off) * 2, qfh[ks]);
        ldsm_x4(sb + (AT_QL + off) * 2, qfl[ks]);
    }

    float of[8][4] = {};
    float mrun[2] = {-1e30f, -1e30f};
    float lrun[2] = {0.0f, 0.0f};

    for (int kb = 0; kb < SEQ; kb += 64) {
        __syncthreads();   // all warps done with previous K/V before overwrite
#pragma unroll
        for (int i = 0; i < 2; i++) {
            const int idx = i * 256 + tid;
            const int row = idx >> 3;
            const int c   = (idx & 7) * 8;
            *(uint4*)&sm[AT_KH + row * 72 + c] = *(const uint4*)(Kh + (size_t)(kb + row) * DHD + c);
            *(uint4*)&sm[AT_KL + row * 72 + c] = *(const uint4*)(Kl + (size_t)(kb + row) * DHD + c);
            *(uint4*)&sm[AT_VH + row * 72 + c] = *(const uint4*)(Vh + (size_t)(kb + row) * DHD + c);
            *(uint4*)&sm[AT_VL + row * 72 + c] = *(const uint4*)(Vl + (size_t)(kb + row) * DHD + c);
        }
        if (tid < 64)
            Mkf[tid] = -10000.0f * (1.0f - (float)mask[b * SEQ + kb + tid]);
        __syncthreads();

        // ---- S = Q K^T (m16 x n64, k=dh=64, hi/lo 3-MMA) ----
        float sf[8][4] = {};
#pragma unroll
        for (int ks = 0; ks < 4; ks++) {
            uint32_t bh[8][2], bl[8][2];
#pragma unroll
            for (int nh = 0; nh < 4; nh++) {
                const uint32_t rowB = nh * 16 + (l & 7) + (l >> 4) * 8;
                const uint32_t kB   = ks * 16 + ((l >> 3) & 1) * 8;
                const uint32_t off  = rowB * 72 + kB;
                uint32_t q[4];
                ldsm_x4(sb + (AT_KH + off) * 2, q);
                bh[nh * 2][0] = q[0]; bh[nh * 2][1] = q[1];
                bh[nh * 2 + 1][0] = q[2]; bh[nh * 2 + 1][1] = q[3];
                ldsm_x4(sb + (AT_KL + off) * 2, q);
                bl[nh * 2][0] = q[0]; bl[nh * 2][1] = q[1];
                bl[nh * 2 + 1][0] = q[2]; bl[nh * 2 + 1][1] = q[3];
            }
#pragma unroll
            for (int nf = 0; nf < 8; nf++) {
                mma16816(sf[nf], qfh[ks], bh[nf]);
                mma16816(sf[nf], qfh[ks], bl[nf]);
                mma16816(sf[nf], qfl[ks], bh[nf]);
            }
        }

        // ---- online softmax (rows live in 4-lane groups; shuffle-reduce) ----
        float mk0[8], mk1[8];
#pragma unroll
        for (int nf = 0; nf < 8; nf++) {
            const float2 m2 = *(const float2*)&Mkf[nf * 8 + (l & 3) * 2];
            mk0[nf] = m2.x; mk1[nf] = m2.y;
        }
#pragma unroll
        for (int i = 0; i < 2; i++) {
            float mx = -1e30f;
#pragma unroll
            for (int nf = 0; nf < 8; nf++) {
                sf[nf][i * 2]     = sf[nf][i * 2]     * 0.125f + mk0[nf];
                sf[nf][i * 2 + 1] = sf[nf][i * 2 + 1] * 0.125f + mk1[nf];
                mx = fmaxf(mx, fmaxf(sf[nf][i * 2], sf[nf][i * 2 + 1]));
            }
            mx = fmaxf(mx, __shfl_xor_sync(0xffffffffu, mx, 1));
            mx = fmaxf(mx, __shfl_xor_sync(0xffffffffu, mx, 2));
            const float mnew = fmaxf(mrun[i], mx);
            const float fac  = __expf(mrun[i] - mnew);
            mrun[i] = mnew;
            float rs = 0.0f;
#pragma unroll
            for (int nf = 0; nf < 8; nf++) {
                const float p0 = __expf(sf[nf][i * 2]     - mnew);
                const float p1 = __expf(sf[nf][i * 2 + 1] - mnew);
                sf[nf][i * 2] = p0; sf[nf][i * 2 + 1] = p1;
                rs += p0 + p1;
            }
            rs += __shfl_xor_sync(0xffffffffu, rs, 1);
            rs += __shfl_xor_sync(0xffffffffu, rs, 2);
            lrun[i] = lrun[i] * fac + rs;
#pragma unroll
            for (int nj = 0; nj < 8; nj++) {
                of[nj][i * 2] *= fac; of[nj][i * 2 + 1] *= fac;
            }
        }

        // ---- repack P (fp32 S frags) into bf16 hi/lo A-frags ----
        uint32_t ph[4][4], pl[4][4];
#pragma unroll
        for (int ks = 0; ks < 4; ks++) {
#pragma unroll
            for (int part = 0; part < 4; part++) {
                const int nf = ks * 2 + (part >> 1);
                const int ri = part & 1;
                const float v0 = sf[nf][ri * 2];
                const float v1 = sf[nf][ri * 2 + 1];
                const __nv_bfloat16 h0 = __float2bfloat16(v0);
                const __nv_bfloat16 h1 = __float2bfloat16(v1);
                ph[ks][part] = pack_bf2(h0, h1);
                pl[ks][part] = pack_bf2(__float2bfloat16(v0 - __bfloat162float(h0)),
                                        __float2bfloat16(v1 - __bfloat162float(h1)));
            }
        }

        // ---- O += P V (k=64 keys, V via ldmatrix.trans, hi/lo 3-MMA) ----
#pragma unroll
        for (int ks = 0; ks < 4; ks++) {
            uint32_t vh[8][2], vl[8][2];
#pragma unroll
            for (int njp = 0; njp < 4; njp++) {
                const uint32_t rowV = ks * 16 + (l & 15);
                const uint32_t colV = (uint32_t)(njp * 2 + (l >> 4)) * 8;
                const uint32_t off  = rowV * 72 + colV;
                uint32_t q[4];
                ldsm_x4_t(sb + (AT_VH + off) * 2, q);
                vh[njp * 2][0] = q[0]; vh[njp * 2][1] = q[1];
                vh[njp * 2 + 1][0] = q[2]; vh[njp * 2 + 1][1] = q[3];
                ldsm_x4_t(sb + (AT_VL + off) * 2, q);
                vl[njp * 2][0] = q[0]; vl[njp * 2][1] = q[1];
                vl[njp * 2 + 1][0] = q[2]; vl[njp * 2 + 1][1] = q[3];
            }
#pragma unroll
            for (int nj = 0; nj < 8; nj++) {
                mma16816(of[nj], ph[ks], vh[nj]);
                mma16816(of[nj], ph[ks], vl[nj]);
                mma16816(of[nj], pl[ks], vh[nj]);
            }
        }
    }

    // ---- epilogue: O / l -> out[b][s][h*64+dh] ----
#pragma unroll
    for (int i = 0; i < 2; i++) {
        const float inv = 1.0f / lrun[i];
        const int row = qt * 128 + w * 16 + (l >> 2) + i * 8;
        const size_t ob = ((size_t)(b * SEQ + row)) * DIM + h * DHD;
#pragma unroll
        for (int nj = 0; nj < 8; nj++) {
            const int dcol = nj * 8 + (l & 3) * 2;
            float2 o;
            o.x = of[nj][i * 2]     * inv;
            o.y = of[nj][i * 2 + 1] * inv;
            *(float2*)&out[ob + dcol] = o;
        }
    }
}

// ---------------------------------------------------------------------------
// Launch
// ---------------------------------------------------------------------------
extern "C" void kernel_launch(void* const* d_in, const int* in_sizes, int n_in,
                              void* d_out, int out_size)
{
    const float* x    = (const float*)d_in[0];
    const int*   mask = (const int*)  d_in[1];
    const float* Wq   = (const float*)d_in[2];
    const float* bq   = (const float*)d_in[3];
    const float* Wk   = (const float*)d_in[4];
    const float* bk   = (const float*)d_in[5];
    const float* Wv   = (const float*)d_in[6];
    const float* bv   = (const float*)d_in[7];
    float* out = (float*)d_out;

    // Split x into bf16 hi/lo
    cvt_x_kernel<<<MTOT * DIM / 4 / 256, 256>>>(x);

    // Transpose + split W into bf16 hi/lo [n][k]
    dim3 gw(DIM / 32, DIM / 32, 3);
    cvt_w_kernel<<<gw, dim3(32, 8)>>>(Wq, Wk, Wv);

    // QKV projection on mma.sync
    cudaFuncSetAttribute(qkv_mma_kernel,
                         cudaFuncAttributeMaxDynamicSharedMemorySize, PJ_SMEM_BYTES);
    dim3 g1(DIM / 64, MTOT / 128, 3);
    qkv_mma_kernel<<<g1, 256, PJ_SMEM_BYTES>>>(bq, bk, bv);

    // Attention on mma.sync
    cudaFuncSetAttribute(attn_mma_kernel,
                         cudaFuncAttributeMaxDynamicSharedMemorySize, AT_SMEM_BYTES);
    dim3 g2(SEQ / 128, NH, BD);
    attn_mma_kernel<<<g2, 256, AT_SMEM_BYTES>>>(mask, out);
}

// round 15
// speedup vs baseline: 3.0268x; 1.1983x over previous
#include <cuda_runtime.h>
#include <cuda_bf16.h>
#include <cstdint>

// Problem constants
#define BD   2
#define SEQ  2048
#define DIM  1024
#define NH   16
#define DHD  64
#define MTOT (BD * SEQ)   // 4096 tokens

// Scratch (device globals; no allocation allowed).
__device__ __nv_bfloat16 g_x_hi[MTOT * DIM];
__device__ __nv_bfloat16 g_x_lo[MTOT * DIM];
__device__ __nv_bfloat16 g_w_hi[3 * DIM * DIM];   // [which][n][k]  (W transposed)
__device__ __nv_bfloat16 g_w_lo[3 * DIM * DIM];
__device__ __nv_bfloat16 g_qh[MTOT * DIM];
__device__ __nv_bfloat16 g_ql[MTOT * DIM];
__device__ __nv_bfloat16 g_kh[MTOT * DIM];
__device__ __nv_bfloat16 g_kl[MTOT * DIM];
__device__ __nv_bfloat16 g_vh[MTOT * DIM];
__device__ __nv_bfloat16 g_vl[MTOT * DIM];

// ---------------------------------------------------------------------------
// PTX helpers (all sm_80+ — compile on plain compute_103)
// ---------------------------------------------------------------------------
__device__ __forceinline__ uint32_t smem_u32(const void* p) {
    uint32_t a;
    asm("{ .reg .u64 t; cvta.to.shared.u64 t, %1; cvt.u32.u64 %0, t; }"
        : "=r"(a) : "l"(p));
    return a;
}
__device__ __forceinline__ void ldsm_x4(uint32_t addr, uint32_t* r) {
    asm volatile("ldmatrix.sync.aligned.m8n8.x4.shared.b16 {%0,%1,%2,%3}, [%4];"
        : "=r"(r[0]), "=r"(r[1]), "=r"(r[2]), "=r"(r[3]) : "r"(addr));
}
__device__ __forceinline__ void ldsm_x4_t(uint32_t addr, uint32_t* r) {
    asm volatile("ldmatrix.sync.aligned.m8n8.x4.trans.shared.b16 {%0,%1,%2,%3}, [%4];"
        : "=r"(r[0]), "=r"(r[1]), "=r"(r[2]), "=r"(r[3]) : "r"(addr));
}
__device__ __forceinline__ void mma16816(float* d, const uint32_t* a, const uint32_t* b) {
    asm volatile(
        "mma.sync.aligned.m16n8k16.row.col.f32.bf16.bf16.f32 "
        "{%0,%1,%2,%3}, {%4,%5,%6,%7}, {%8,%9}, {%0,%1,%2,%3};"
        : "+f"(d[0]), "+f"(d[1]), "+f"(d[2]), "+f"(d[3])
        : "r"(a[0]), "r"(a[1]), "r"(a[2]), "r"(a[3]), "r"(b[0]), "r"(b[1]));
}
__device__ __forceinline__ uint32_t pack_bf2(__nv_bfloat16 a, __nv_bfloat16 b) {
    __nv_bfloat162 t = __halves2bfloat162(a, b);
    return *reinterpret_cast<uint32_t*>(&t);
}
#define CP_ASYNC16(dst, src) \
    asm volatile("cp.async.cg.shared.global [%0], [%1], 16;" :: "r"(dst), "l"(src))
#define CP_COMMIT() asm volatile("cp.async.commit_group;" ::: "memory")
#define CP_WAIT0()  asm volatile("cp.async.wait_group 0;" ::: "memory")

// ---------------------------------------------------------------------------
// Prep 1: x (fp32) -> bf16 hi/lo split
// ---------------------------------------------------------------------------
__global__ __launch_bounds__(256)
void cvt_x_kernel(const float* __restrict__ x)
{
    const int i = blockIdx.x * 256 + threadIdx.x;
    const float4 v = ((const float4*)x)[i];
    const __nv_bfloat16 h0 = __float2bfloat16(v.x);
    const __nv_bfloat16 h1 = __float2bfloat16(v.y);
    const __nv_bfloat16 h2 = __float2bfloat16(v.z);
    const __nv_bfloat16 h3 = __float2bfloat16(v.w);
    const __nv_bfloat16 l0 = __float2bfloat16(v.x - __bfloat162float(h0));
    const __nv_bfloat16 l1 = __float2bfloat16(v.y - __bfloat162float(h1));
    const __nv_bfloat16 l2 = __float2bfloat16(v.z - __bfloat162float(h2));
    const __nv_bfloat16 l3 = __float2bfloat16(v.w - __bfloat162float(h3));
    ((__nv_bfloat162*)g_x_hi)[2 * i]     = __halves2bfloat162(h0, h1);
    ((__nv_bfloat162*)g_x_hi)[2 * i + 1] = __halves2bfloat162(h2, h3);
    ((__nv_bfloat162*)g_x_lo)[2 * i]     = __halves2bfloat162(l0, l1);
    ((__nv_bfloat162*)g_x_lo)[2 * i + 1] = __halves2bfloat162(l2, l3);
}

// ---------------------------------------------------------------------------
// Prep 2: W[k][n] (fp32) -> transposed bf16 hi/lo [n][k]
// ---------------------------------------------------------------------------
__global__ __launch_bounds__(256)
void cvt_w_kernel(const float* __restrict__ Wq, const float* __restrict__ Wk,
                  const float* __restrict__ Wv)
{
    __shared__ float t[32][33];
    const int which = blockIdx.z;
    const float* __restrict__ W = (which == 0) ? Wq : (which == 1) ? Wk : Wv;
    const int n0 = blockIdx.x * 32;
    const int k0 = blockIdx.y * 32;
    const int tx = threadIdx.x;
    const int ty = threadIdx.y;

#pragma unroll
    for (int j = 0; j < 4; j++)
        t[ty + 8 * j][tx] = W[(k0 + ty + 8 * j) * DIM + n0 + tx];
    __syncthreads();

    __nv_bfloat16* __restrict__ gh = g_w_hi + which * DIM * DIM;
    __nv_bfloat16* __restrict__ gl = g_w_lo + which * DIM * DIM;
#pragma unroll
    for (int j = 0; j < 4; j++) {
        const int n = n0 + ty + 8 * j;
        const int k = k0 + tx;
        const float w = t[tx][ty + 8 * j];
        const __nv_bfloat16 h = __float2bfloat16(w);
        const __nv_bfloat16 l = __float2bfloat16(w - __bfloat162float(h));
        gh[n * DIM + k] = h;
        gl[n * DIM + k] = l;
    }
}

// ---------------------------------------------------------------------------
// Kernel 1: QKV projection, mma.sync bf16 hi/lo, cp.async 2-stage pipeline.
// BM=128 x BN=64 (one head), BK=64, 256 threads, warp tile 32x32.
// smem stage (bf16, stride 72): AH[128*72] AL[128*72] BH[64*72] BL[64*72]
// ---------------------------------------------------------------------------
#define PJ_STG(s) ((s) * 384 * 72)
#define PJ_AH(s)  (PJ_STG(s))
#define PJ_AL(s)  (PJ_STG(s) + 128 * 72)
#define PJ_BH(s)  (PJ_STG(s) + 256 * 72)
#define PJ_BL(s)  (PJ_STG(s) + 320 * 72)
#define PJ_SMEM_BYTES (2 * 384 * 72 * 2)   // 110592

__device__ __forceinline__ void pj_issue(uint32_t sb, int s, int k0,
    const __nv_bfloat16* __restrict__ Ah, const __nv_bfloat16* __restrict__ Al,
    const __nv_bfloat16* __restrict__ Bh, const __nv_bfloat16* __restrict__ Bl,
    int tid)
{
#pragma unroll
    for (int i = 0; i < 4; i++) {                  // A: 128 rows x 8 chunks
        const int slot = i * 256 + tid;
        const int row = slot >> 3;
        const int c   = (slot & 7) * 8;
        const size_t go = (size_t)row * DIM + k0 + c;
        const uint32_t so = row * 72 + c;
        CP_ASYNC16(sb + (PJ_AH(s) + so) * 2, Ah + go);
        CP_ASYNC16(sb + (PJ_AL(s) + so) * 2, Al + go);
    }
#pragma unroll
    for (int i = 0; i < 2; i++) {                  // B: 64 rows x 8 chunks
        const int slot = i * 256 + tid;
        const int row = slot >> 3;
        const int c   = (slot & 7) * 8;
        const size_t go = (size_t)row * DIM + k0 + c;
        const uint32_t so = row * 72 + c;
        CP_ASYNC16(sb + (PJ_BH(s) + so) * 2, Bh + go);
        CP_ASYNC16(sb + (PJ_BL(s) + so) * 2, Bl + go);
    }
}

__global__ __launch_bounds__(256)
void qkv_mma_kernel(const float* __restrict__ bq, const float* __restrict__ bk,
                    const float* __restrict__ bv)
{
    extern __shared__ __nv_bfloat16 sm[];
    const int tid = threadIdx.x;
    const int l   = tid & 31;
    const int wid = tid >> 5;
    const int which = blockIdx.z;
    const int n0 = blockIdx.x * 64;
    const int m0 = blockIdx.y * 128;

    const __nv_bfloat16* __restrict__ Ah = g_x_hi + (size_t)m0 * DIM;
    const __nv_bfloat16* __restrict__ Al = g_x_lo + (size_t)m0 * DIM;
    const __nv_bfloat16* __restrict__ Bh = g_w_hi + (size_t)which * DIM * DIM + (size_t)n0 * DIM;
    const __nv_bfloat16* __restrict__ Bl = g_w_lo + (size_t)which * DIM * DIM + (size_t)n0 * DIM;

    const uint32_t sb = smem_u32(sm);
    const int mbase = (wid >> 1) * 32;
    const int nbase = (wid & 1) * 32;

    float acc[2][4][4] = {};

    pj_issue(sb, 0, 0, Ah, Al, Bh, Bl, tid);
    CP_COMMIT();

    for (int c = 0; c < 16; c++) {
        const int s = c & 1;
        CP_WAIT0();
        __syncthreads();
        if (c + 1 < 16) {
            pj_issue(sb, s ^ 1, (c + 1) * 64, Ah, Al, Bh, Bl, tid);
            CP_COMMIT();
        }

#pragma unroll
        for (int ks = 0; ks < 4; ks++) {
            uint32_t ah[2][4], al[2][4], bh[4][2], bl[4][2];
#pragma unroll
            for (int mt = 0; mt < 2; mt++) {
                const uint32_t off = (uint32_t)(mbase + mt * 16 + (l & 15)) * 72
                                   + ks * 16 + (l >> 4) * 8;
                ldsm_x4(sb + (PJ_AH(s) + off) * 2, ah[mt]);
                ldsm_x4(sb + (PJ_AL(s) + off) * 2, al[mt]);
            }
#pragma unroll
            for (int nh = 0; nh < 2; nh++) {
                const uint32_t rowB = nbase + nh * 16 + (l & 7) + (l >> 4) * 8;
                const uint32_t kB   = ks * 16 + ((l >> 3) & 1) * 8;
                const uint32_t off  = rowB * 72 + kB;
                uint32_t q[4];
                ldsm_x4(sb + (PJ_BH(s) + off) * 2, q);
                bh[nh * 2][0] = q[0]; bh[nh * 2][1] = q[1];
                bh[nh * 2 + 1][0] = q[2]; bh[nh * 2 + 1][1] = q[3];
                ldsm_x4(sb + (PJ_BL(s) + off) * 2, q);
                bl[nh * 2][0] = q[0]; bl[nh * 2][1] = q[1];
                bl[nh * 2 + 1][0] = q[2]; bl[nh * 2 + 1][1] = q[3];
            }
#pragma unroll
            for (int mt = 0; mt < 2; mt++)
#pragma unroll
                for (int nf = 0; nf < 4; nf++) {
                    mma16816(acc[mt][nf], ah[mt], bh[nf]);
                    mma16816(acc[mt][nf], ah[mt], bl[nf]);
                    mma16816(acc[mt][nf], al[mt], bh[nf]);
                }
        }
    }

    // Epilogue: bias, hi/lo split, store bf162 pairs head-major.
    const float* __restrict__ bias = (which == 0) ? bq : (which == 1) ? bk : bv;
    __nv_bfloat16* __restrict__ dsth = (which == 0) ? g_qh : (which == 1) ? g_kh : g_vh;
    __nv_bfloat16* __restrict__ dstl = (which == 0) ? g_ql : (which == 1) ? g_kl : g_vl;
    const int h = n0 >> 6;

#pragma unroll
    for (int mt = 0; mt < 2; mt++)
#pragma unroll
        for (int i = 0; i < 2; i++) {
            const int m = m0 + mbase + mt * 16 + (l >> 2) + i * 8;
            const int b = m >> 11;
            const int s = m & (SEQ - 1);
            const size_t base = ((size_t)((b * NH + h) * SEQ) + s) * DHD;
#pragma unroll
            for (int nf = 0; nf < 4; nf++) {
                const int dcol = nbase + nf * 8 + (l & 3) * 2;
                const float v0 = acc[mt][nf][i * 2]     + bias[n0 + dcol];
                const float v1 = acc[mt][nf][i * 2 + 1] + bias[n0 + dcol + 1];
                const __nv_bfloat16 h0 = __float2bfloat16(v0);
                const __nv_bfloat16 h1 = __float2bfloat16(v1);
                const __nv_bfloat16 q0 = __float2bfloat16(v0 - __bfloat162float(h0));
                const __nv_bfloat16 q1 = __float2bfloat16(v1 - __bfloat162float(h1));
                *(__nv_bfloat162*)&dsth[base + dcol] = __halves2bfloat162(h0, h1);
                *(__nv_bfloat162*)&dstl[base + dcol] = __halves2bfloat162(q0, q1);
            }
        }
}

// ---------------------------------------------------------------------------
// Kernel 2: flash attention, mma.sync bf16 hi/lo, cp.async 2-stage K/V ring.
// CTA = 64 queries x (h, b), 4 warps (128 threads, 2 CTAs/SM).
// Warp w owns rows w*16..w*16+15 and the full 64-key range per tile.
// smem (bf16, stride 72): Qh Ql [64*72] | 2 stages x {Kh Kl Vh Vl}[64*72] | Mk[2][64] f32
// ---------------------------------------------------------------------------
#define AT_QH 0
#define AT_QL (64 * 72)
#define AT_STG(s) (128 * 72 + (s) * (4 * 64 * 72))
#define AT_KH(s) (AT_STG(s))
#define AT_KL(s) (AT_STG(s) + 64 * 72)
#define AT_VH(s) (AT_STG(s) + 2 * 64 * 72)
#define AT_VL(s) (AT_STG(s) + 3 * 64 * 72)
#define AT_MK    (128 * 72 + 8 * 64 * 72)
#define AT_SMEM_BYTES ((128 * 72 + 8 * 64 * 72) * 2 + 2 * 64 * 4)  // 92672

__device__ __forceinline__ void at_issue(uint32_t sb, int s, int kb,
    const __nv_bfloat16* __restrict__ Kh, const __nv_bfloat16* __restrict__ Kl,
    const __nv_bfloat16* __restrict__ Vh, const __nv_bfloat16* __restrict__ Vl,
    int tid)
{
#pragma unroll
    for (int i = 0; i < 4; i++) {                  // 64 rows x 8 chunks
        const int slot = i * 128 + tid;
        const int row = slot >> 3;
        const int c   = (slot & 7) * 8;
        const size_t go = (size_t)(kb + row) * DHD + c;
        const uint32_t so = row * 72 + c;
        CP_ASYNC16(sb + (AT_KH(s) + so) * 2, Kh + go);
        CP_ASYNC16(sb + (AT_KL(s) + so) * 2, Kl + go);
        CP_ASYNC16(sb + (AT_VH(s) + so) * 2, Vh + go);
        CP_ASYNC16(sb + (AT_VL(s) + so) * 2, Vl + go);
    }
}

__global__ __launch_bounds__(128, 2)
void attn_mma_kernel(const int* __restrict__ mask, float* __restrict__ out)
{
    extern __shared__ __nv_bfloat16 sm[];
    float* Mkf = (float*)(sm + AT_MK);

    const int tid = threadIdx.x;
    const int l   = tid & 31;
    const int w   = tid >> 5;
    const int qt  = blockIdx.x;
    const int h   = blockIdx.y;
    const int b   = blockIdx.z;

    const size_t headoff = (size_t)((b * NH + h) * SEQ) * DHD;
    const __nv_bfloat16* __restrict__ Qh = g_qh + headoff + (size_t)qt * 64 * DHD;
    const __nv_bfloat16* __restrict__ Ql = g_ql + headoff + (size_t)qt * 64 * DHD;
    const __nv_bfloat16* __restrict__ Kh = g_kh + headoff;
    const __nv_bfloat16* __restrict__ Kl = g_kl + headoff;
    const __nv_bfloat16* __restrict__ Vh = g_vh + headoff;
    const __nv_bfloat16* __restrict__ Vl = g_vl + headoff;
    const uint32_t sb = smem_u32(sm);

    // Preload: Q tile + first K/V tile + first mask slice, one cp.async group.
#pragma unroll
    for (int i = 0; i < 4; i++) {                  // Q: 64 rows x 8 chunks, hi+lo
        const int slot = i * 128 + tid;
        const int row = slot >> 3;
        const int c   = (slot & 7) * 8;
        const size_t go = (size_t)row * DHD + c;
        const uint32_t so = row * 72 + c;
        CP_ASYNC16(sb + (AT_QH + so) * 2, Qh + go);
        CP_ASYNC16(sb + (AT_QL + so) * 2, Ql + go);
    }
    at_issue(sb, 0, 0, Kh, Kl, Vh, Vl, tid);
    if (tid < 64)
        Mkf[tid] = -10000.0f * (1.0f - (float)mask[b * SEQ + tid]);
    CP_COMMIT();
    CP_WAIT0();
    __syncthreads();

    // Lift this warp's Q fragments into registers (persistent).
    uint32_t qfh[4][4], qfl[4][4];
#pragma unroll
    for (int ks = 0; ks < 4; ks++) {
        const uint32_t off = (uint32_t)(w * 16 + (l & 15)) * 72 + ks * 16 + (l >> 4) * 8;
        ldsm_x4(sb + (AT_QH + off) * 2, qfh[ks]);
        ldsm_x4(sb + (AT_QL + off) * 2, qfl[ks]);
    }

    float of[8][4] = {};
    float mrun[2] = {-1e30f, -1e30f};
    float lrun[2] = {0.0f, 0.0f};

    for (int t = 0; t < SEQ / 64; t++) {
        const int s = t & 1;
        if (t > 0) {           // data for tile t is the only group in flight
            CP_WAIT0();
            __syncthreads();
        }
        if (t + 1 < SEQ / 64) {   // prefetch next tile into the other stage
            at_issue(sb, s ^ 1, (t + 1) * 64, Kh, Kl, Vh, Vl, tid);
            if (tid < 64)
                Mkf[(s ^ 1) * 64 + tid] =
                    -10000.0f * (1.0f - (float)mask[b * SEQ + (t + 1) * 64 + tid]);
            CP_COMMIT();
        }

        // ---- S = Q K^T (m16 x n64, k=64, hi/lo 3-MMA) ----
        float sf[8][4] = {};
#pragma unroll
        for (int ks = 0; ks < 4; ks++) {
            uint32_t bh[8][2], bl[8][2];
#pragma unroll
            for (int nh = 0; nh < 4; nh++) {
                const uint32_t rowB = nh * 16 + (l & 7) + (l >> 4) * 8;
                const uint32_t kB   = ks * 16 + ((l >> 3) & 1) * 8;
                const uint32_t off  = rowB * 72 + kB;
                uint32_t q[4];
                ldsm_x4(sb + (AT_KH(s) + off) * 2, q);
                bh[nh * 2][0] = q[0]; bh[nh * 2][1] = q[1];
                bh[nh * 2 + 1][0] = q[2]; bh[nh * 2 + 1][1] = q[3];
                ldsm_x4(sb + (AT_KL(s) + off) * 2, q);
                bl[nh * 2][0] = q[0]; bl[nh * 2][1] = q[1];
                bl[nh * 2 + 1][0] = q[2]; bl[nh * 2 + 1][1] = q[3];
            }
#pragma unroll
            for (int nf = 0; nf < 8; nf++) {
                mma16816(sf[nf], qfh[ks], bh[nf]);
                mma16816(sf[nf], qfh[ks], bl[nf]);
                mma16816(sf[nf], qfl[ks], bh[nf]);
            }
        }

        // ---- online softmax (rows in 4-lane groups) ----
        float mk0[8], mk1[8];
#pragma unroll
        for (int nf = 0; nf < 8; nf++) {
            const float2 m2 = *(const float2*)&Mkf[s * 64 + nf * 8 + (l & 3) * 2];
            mk0[nf] = m2.x; mk1[nf] = m2.y;
        }
#pragma unroll
        for (int i = 0; i < 2; i++) {
            float mx = -1e30f;
#pragma unroll
            for (int nf = 0; nf < 8; nf++) {
                sf[nf][i * 2]     = sf[nf][i * 2]     * 0.125f + mk0[nf];
                sf[nf][i * 2 + 1] = sf[nf][i * 2 + 1] * 0.125f + mk1[nf];
                mx = fmaxf(mx, fmaxf(sf[nf][i * 2], sf[nf][i * 2 + 1]));
            }
            mx = fmaxf(mx, __shfl_xor_sync(0xffffffffu, mx, 1));
            mx = fmaxf(mx, __shfl_xor_sync(0xffffffffu, mx, 2));
            const float mnew = fmaxf(mrun[i], mx);
            const float fac  = __expf(mrun[i] - mnew);
            mrun[i] = mnew;
            float rs = 0.0f;
#pragma unroll
            for (int nf = 0; nf < 8; nf++) {
                const float p0 = __expf(sf[nf][i * 2]     - mnew);
                const float p1 = __expf(sf[nf][i * 2 + 1] - mnew);
                sf[nf][i * 2] = p0; sf[nf][i * 2 + 1] = p1;
                rs += p0 + p1;
            }
            rs += __shfl_xor_sync(0xffffffffu, rs, 1);
            rs += __shfl_xor_sync(0xffffffffu, rs, 2);
            lrun[i] = lrun[i] * fac + rs;
#pragma unroll
            for (int nj = 0; nj < 8; nj++) {
                of[nj][i * 2] *= fac; of[nj][i * 2 + 1] *= fac;
            }
        }

        // ---- repack P into bf16 hi/lo A-frags ----
        uint32_t ph[4][4], pl[4][4];
#pragma unroll
        for (int ks = 0; ks < 4; ks++) {
#pragma unroll
            for (int part = 0; part < 4; part++) {
                const int nf = ks * 2 + (part >> 1);
                const int ri = part & 1;
                const float v0 = sf[nf][ri * 2];
                const float v1 = sf[nf][ri * 2 + 1];
                const __nv_bfloat16 h0 = __float2bfloat16(v0);
                const __nv_bfloat16 h1 = __float2bfloat16(v1);
                ph[ks][part] = pack_bf2(h0, h1);
                pl[ks][part] = pack_bf2(__float2bfloat16(v0 - __bfloat162float(h0)),
                                        __float2bfloat16(v1 - __bfloat162float(h1)));
            }
        }

        // ---- O += P V (V via ldmatrix.trans, hi/lo 3-MMA) ----
#pragma unroll
        for (int ks = 0; ks < 4; ks++) {
            uint32_t vh[8][2], vl[8][2];
#pragma unroll
            for (int njp = 0; njp < 4; njp++) {
                const uint32_t rowV = ks * 16 + (l & 15);
                const uint32_t colV = (uint32_t)(njp * 2 + (l >> 4)) * 8;
                const uint32_t off  = rowV * 72 + colV;
                uint32_t q[4];
                ldsm_x4_t(sb + (AT_VH(s) + off) * 2, q);
                vh[njp * 2][0] = q[0]; vh[njp * 2][1] = q[1];
                vh[njp * 2 + 1][0] = q[2]; vh[njp * 2 + 1][1] = q[3];
                ldsm_x4_t(sb + (AT_VL(s) + off) * 2, q);
                vl[njp * 2][0] = q[0]; vl[njp * 2][1] = q[1];
                vl[njp * 2 + 1][0] = q[2]; vl[njp * 2 + 1][1] = q[3];
            }
#pragma unroll
            for (int nj = 0; nj < 8; nj++) {
                mma16816(of[nj], ph[ks], vh[nj]);
                mma16816(of[nj], ph[ks], vl[nj]);
                mma16816(of[nj], pl[ks], vh[nj]);
            }
        }
    }

    // ---- epilogue: O / l -> out[b][s][h*64+dh] ----
#pragma unroll
    for (int i = 0; i < 2; i++) {
        const float inv = 1.0f / lrun[i];
        const int row = qt * 64 + w * 16 + (l >> 2) + i * 8;
        const size_t ob = ((size_t)(b * SEQ + row)) * DIM + h * DHD;
#pragma unroll
        for (int nj = 0; nj < 8; nj++) {
            const int dcol = nj * 8 + (l & 3) * 2;
            float2 o;
            o.x = of[nj][i * 2]     * inv;
            o.y = of[nj][i * 2 + 1] * inv;
            *(float2*)&out[ob + dcol] = o;
        }
    }
}

// ---------------------------------------------------------------------------
// Launch
// ---------------------------------------------------------------------------
extern "C" void kernel_launch(void* const* d_in, const int* in_sizes, int n_in,
                              void* d_out, int out_size)
{
    const float* x    = (const float*)d_in[0];
    const int*   mask = (const int*)  d_in[1];
    const float* Wq   = (const float*)d_in[2];
    const float* bq   = (const float*)d_in[3];
    const float* Wk   = (const float*)d_in[4];
    const float* bk   = (const float*)d_in[5];
    const float* Wv   = (const float*)d_in[6];
    const float* bv   = (const float*)d_in[7];
    float* out = (float*)d_out;

    cvt_x_kernel<<<MTOT * DIM / 4 / 256, 256>>>(x);

    dim3 gw(DIM / 32, DIM / 32, 3);
    cvt_w_kernel<<<gw, dim3(32, 8)>>>(Wq, Wk, Wv);

    cudaFuncSetAttribute(qkv_mma_kernel,
                         cudaFuncAttributeMaxDynamicSharedMemorySize, PJ_SMEM_BYTES);
    dim3 g1(DIM / 64, MTOT / 128, 3);
    qkv_mma_kernel<<<g1, 256, PJ_SMEM_BYTES>>>(bq, bk, bv);

    cudaFuncSetAttribute(attn_mma_kernel,
                         cudaFuncAttributeMaxDynamicSharedMemorySize, AT_SMEM_BYTES);
    dim3 g2(SEQ / 64, NH, BD);
    attn_mma_kernel<<<g2, 128, AT_SMEM_BYTES>>>(mask, out);
}

// round 16
// speedup vs baseline: 4.4738x; 1.4781x over previous
#include <cuda_runtime.h>
#include <cuda_bf16.h>
#include <cuda_fp16.h>
#include <cstdint>

// Problem constants
#define BD   2
#define SEQ  2048
#define DIM  1024
#define NH   16
#define DHD  64
#define MTOT (BD * SEQ)   // 4096 tokens

// Scratch (device globals; no allocation allowed).
__device__ __nv_bfloat16 g_x_hi[MTOT * DIM];
__device__ __nv_bfloat16 g_x_lo[MTOT * DIM];
__device__ __nv_bfloat16 g_w_hi[3 * DIM * DIM];   // [which][n][k]  (W transposed)
__device__ __nv_bfloat16 g_w_lo[3 * DIM * DIM];
__device__ __half g_qf[MTOT * DIM];   // Q/K/V head-major [b,h,s,dh], single fp16
__device__ __half g_kf[MTOT * DIM];
__device__ __half g_vf[MTOT * DIM];

// ---------------------------------------------------------------------------
// PTX helpers (all sm_80+ — compile on plain compute_103)
// ---------------------------------------------------------------------------
__device__ __forceinline__ uint32_t smem_u32(const void* p) {
    uint32_t a;
    asm("{ .reg .u64 t; cvta.to.shared.u64 t, %1; cvt.u32.u64 %0, t; }"
        : "=r"(a) : "l"(p));
    return a;
}
__device__ __forceinline__ void ldsm_x4(uint32_t addr, uint32_t* r) {
    asm volatile("ldmatrix.sync.aligned.m8n8.x4.shared.b16 {%0,%1,%2,%3}, [%4];"
        : "=r"(r[0]), "=r"(r[1]), "=r"(r[2]), "=r"(r[3]) : "r"(addr));
}
__device__ __forceinline__ void ldsm_x4_t(uint32_t addr, uint32_t* r) {
    asm volatile("ldmatrix.sync.aligned.m8n8.x4.trans.shared.b16 {%0,%1,%2,%3}, [%4];"
        : "=r"(r[0]), "=r"(r[1]), "=r"(r[2]), "=r"(r[3]) : "r"(addr));
}
// bf16 MMA (projection path)
__device__ __forceinline__ void mma16816(float* d, const uint32_t* a, const uint32_t* b) {
    asm volatile(
        "mma.sync.aligned.m16n8k16.row.col.f32.bf16.bf16.f32 "
        "{%0,%1,%2,%3}, {%4,%5,%6,%7}, {%8,%9}, {%0,%1,%2,%3};"
        : "+f"(d[0]), "+f"(d[1]), "+f"(d[2]), "+f"(d[3])
        : "r"(a[0]), "r"(a[1]), "r"(a[2]), "r"(a[3]), "r"(b[0]), "r"(b[1]));
}
// fp16 MMA (attention path)
__device__ __forceinline__ void mma16816h(float* d, const uint32_t* a, const uint32_t* b) {
    asm volatile(
        "mma.sync.aligned.m16n8k16.row.col.f32.f16.f16.f32 "
        "{%0,%1,%2,%3}, {%4,%5,%6,%7}, {%8,%9}, {%0,%1,%2,%3};"
        : "+f"(d[0]), "+f"(d[1]), "+f"(d[2]), "+f"(d[3])
        : "r"(a[0]), "r"(a[1]), "r"(a[2]), "r"(a[3]), "r"(b[0]), "r"(b[1]));
}
__device__ __forceinline__ uint32_t pack_h2(float a, float b) {
    __half2 t = __floats2half2_rn(a, b);
    return *reinterpret_cast<uint32_t*>(&t);
}
#define CP_ASYNC16(dst, src) \
    asm volatile("cp.async.cg.shared.global [%0], [%1], 16;" :: "r"(dst), "l"(src))
#define CP_COMMIT() asm volatile("cp.async.commit_group;" ::: "memory")
#define CP_WAIT0()  asm volatile("cp.async.wait_group 0;" ::: "memory")

// ---------------------------------------------------------------------------
// Prep 1: x (fp32) -> bf16 hi/lo split
// ---------------------------------------------------------------------------
__global__ __launch_bounds__(256)
void cvt_x_kernel(const float* __restrict__ x)
{
    const int i = blockIdx.x * 256 + threadIdx.x;
    const float4 v = ((const float4*)x)[i];
    const __nv_bfloat16 h0 = __float2bfloat16(v.x);
    const __nv_bfloat16 h1 = __float2bfloat16(v.y);
    const __nv_bfloat16 h2 = __float2bfloat16(v.z);
    const __nv_bfloat16 h3 = __float2bfloat16(v.w);
    const __nv_bfloat16 l0 = __float2bfloat16(v.x - __bfloat162float(h0));
    const __nv_bfloat16 l1 = __float2bfloat16(v.y - __bfloat162float(h1));
    const __nv_bfloat16 l2 = __float2bfloat16(v.z - __bfloat162float(h2));
    const __nv_bfloat16 l3 = __float2bfloat16(v.w - __bfloat162float(h3));
    ((__nv_bfloat162*)g_x_hi)[2 * i]     = __halves2bfloat162(h0, h1);
    ((__nv_bfloat162*)g_x_hi)[2 * i + 1] = __halves2bfloat162(h2, h3);
    ((__nv_bfloat162*)g_x_lo)[2 * i]     = __halves2bfloat162(l0, l1);
    ((__nv_bfloat162*)g_x_lo)[2 * i + 1] = __halves2bfloat162(l2, l3);
}

// ---------------------------------------------------------------------------
// Prep 2: W[k][n] (fp32) -> transposed bf16 hi/lo [n][k]
// ---------------------------------------------------------------------------
__global__ __launch_bounds__(256)
void cvt_w_kernel(const float* __restrict__ Wq, const float* __restrict__ Wk,
                  const float* __restrict__ Wv)
{
    __shared__ float t[32][33];
    const int which = blockIdx.z;
    const float* __restrict__ W = (which == 0) ? Wq : (which == 1) ? Wk : Wv;
    const int n0 = blockIdx.x * 32;
    const int k0 = blockIdx.y * 32;
    const int tx = threadIdx.x;
    const int ty = threadIdx.y;

#pragma unroll
    for (int j = 0; j < 4; j++)
        t[ty + 8 * j][tx] = W[(k0 + ty + 8 * j) * DIM + n0 + tx];
    __syncthreads();

    __nv_bfloat16* __restrict__ gh = g_w_hi + which * DIM * DIM;
    __nv_bfloat16* __restrict__ gl = g_w_lo + which * DIM * DIM;
#pragma unroll
    for (int j = 0; j < 4; j++) {
        const int n = n0 + ty + 8 * j;
        const int k = k0 + tx;
        const float w = t[tx][ty + 8 * j];
        const __nv_bfloat16 h = __float2bfloat16(w);
        const __nv_bfloat16 l = __float2bfloat16(w - __bfloat162float(h));
        gh[n * DIM + k] = h;
        gl[n * DIM + k] = l;
    }
}

// ---------------------------------------------------------------------------
// Kernel 1: QKV projection, mma.sync bf16 hi/lo 3-MMA (full precision math),
// epilogue writes SINGLE fp16 Q/K/V head-major.
// BM=128 x BN=64 (one head), BK=64, 256 threads, warp tile 32x32.
// ---------------------------------------------------------------------------
#define PJ_STG(s) ((s) * 384 * 72)
#define PJ_AH(s)  (PJ_STG(s))
#define PJ_AL(s)  (PJ_STG(s) + 128 * 72)
#define PJ_BH(s)  (PJ_STG(s) + 256 * 72)
#define PJ_BL(s)  (PJ_STG(s) + 320 * 72)
#define PJ_SMEM_BYTES (2 * 384 * 72 * 2)   // 110592

__device__ __forceinline__ void pj_issue(uint32_t sb, int s, int k0,
    const __nv_bfloat16* __restrict__ Ah, const __nv_bfloat16* __restrict__ Al,
    const __nv_bfloat16* __restrict__ Bh, const __nv_bfloat16* __restrict__ Bl,
    int tid)
{
#pragma unroll
    for (int i = 0; i < 4; i++) {                  // A: 128 rows x 8 chunks
        const int slot = i * 256 + tid;
        const int row = slot >> 3;
        const int c   = (slot & 7) * 8;
        const size_t go = (size_t)row * DIM + k0 + c;
        const uint32_t so = row * 72 + c;
        CP_ASYNC16(sb + (PJ_AH(s) + so) * 2, Ah + go);
        CP_ASYNC16(sb + (PJ_AL(s) + so) * 2, Al + go);
    }
#pragma unroll
    for (int i = 0; i < 2; i++) {                  // B: 64 rows x 8 chunks
        const int slot = i * 256 + tid;
        const int row = slot >> 3;
        const int c   = (slot & 7) * 8;
        const size_t go = (size_t)row * DIM + k0 + c;
        const uint32_t so = row * 72 + c;
        CP_ASYNC16(sb + (PJ_BH(s) + so) * 2, Bh + go);
        CP_ASYNC16(sb + (PJ_BL(s) + so) * 2, Bl + go);
    }
}

__global__ __launch_bounds__(256)
void qkv_mma_kernel(const float* __restrict__ bq, const float* __restrict__ bk,
                    const float* __restrict__ bv)
{
    extern __shared__ __nv_bfloat16 sm[];
    const int tid = threadIdx.x;
    const int l   = tid & 31;
    const int wid = tid >> 5;
    const int which = blockIdx.z;
    const int n0 = blockIdx.x * 64;
    const int m0 = blockIdx.y * 128;

    const __nv_bfloat16* __restrict__ Ah = g_x_hi + (size_t)m0 * DIM;
    const __nv_bfloat16* __restrict__ Al = g_x_lo + (size_t)m0 * DIM;
    const __nv_bfloat16* __restrict__ Bh = g_w_hi + (size_t)which * DIM * DIM + (size_t)n0 * DIM;
    const __nv_bfloat16* __restrict__ Bl = g_w_lo + (size_t)which * DIM * DIM + (size_t)n0 * DIM;

    const uint32_t sb = smem_u32(sm);
    const int mbase = (wid >> 1) * 32;
    const int nbase = (wid & 1) * 32;

    float acc[2][4][4] = {};

    pj_issue(sb, 0, 0, Ah, Al, Bh, Bl, tid);
    CP_COMMIT();

    for (int c = 0; c < 16; c++) {
        const int s = c & 1;
        CP_WAIT0();
        __syncthreads();
        if (c + 1 < 16) {
            pj_issue(sb, s ^ 1, (c + 1) * 64, Ah, Al, Bh, Bl, tid);
            CP_COMMIT();
        }

#pragma unroll
        for (int ks = 0; ks < 4; ks++) {
            uint32_t ah[2][4], al[2][4], bh[4][2], bl[4][2];
#pragma unroll
            for (int mt = 0; mt < 2; mt++) {
                const uint32_t off = (uint32_t)(mbase + mt * 16 + (l & 15)) * 72
                                   + ks * 16 + (l >> 4) * 8;
                ldsm_x4(sb + (PJ_AH(s) + off) * 2, ah[mt]);
                ldsm_x4(sb + (PJ_AL(s) + off) * 2, al[mt]);
            }
#pragma unroll
            for (int nh = 0; nh < 2; nh++) {
                const uint32_t rowB = nbase + nh * 16 + (l & 7) + (l >> 4) * 8;
                const uint32_t kB   = ks * 16 + ((l >> 3) & 1) * 8;
                const uint32_t off  = rowB * 72 + kB;
                uint32_t q[4];
                ldsm_x4(sb + (PJ_BH(s) + off) * 2, q);
                bh[nh * 2][0] = q[0]; bh[nh * 2][1] = q[1];
                bh[nh * 2 + 1][0] = q[2]; bh[nh * 2 + 1][1] = q[3];
                ldsm_x4(sb + (PJ_BL(s) + off) * 2, q);
                bl[nh * 2][0] = q[0]; bl[nh * 2][1] = q[1];
                bl[nh * 2 + 1][0] = q[2]; bl[nh * 2 + 1][1] = q[3];
            }
#pragma unroll
            for (int mt = 0; mt < 2; mt++)
#pragma unroll
                for (int nf = 0; nf < 4; nf++) {
                    mma16816(acc[mt][nf], ah[mt], bh[nf]);
                    mma16816(acc[mt][nf], ah[mt], bl[nf]);
                    mma16816(acc[mt][nf], al[mt], bh[nf]);
                }
        }
    }

    // Epilogue: bias, single fp16 store head-major.
    const float* __restrict__ bias = (which == 0) ? bq : (which == 1) ? bk : bv;
    __half* __restrict__ dst = (which == 0) ? g_qf : (which == 1) ? g_kf : g_vf;
    const int h = n0 >> 6;

#pragma unroll
    for (int mt = 0; mt < 2; mt++)
#pragma unroll
        for (int i = 0; i < 2; i++) {
            const int m = m0 + mbase + mt * 16 + (l >> 2) + i * 8;
            const int b = m >> 11;
            const int s = m & (SEQ - 1);
            const size_t base = ((size_t)((b * NH + h) * SEQ) + s) * DHD;
#pragma unroll
            for (int nf = 0; nf < 4; nf++) {
                const int dcol = nbase + nf * 8 + (l & 3) * 2;
                const float v0 = acc[mt][nf][i * 2]     + bias[n0 + dcol];
                const float v1 = acc[mt][nf][i * 2 + 1] + bias[n0 + dcol + 1];
                *(uint32_t*)&dst[base + dcol] = pack_h2(v0, v1);
            }
        }
}

// ---------------------------------------------------------------------------
// Kernel 2: flash attention, SINGLE fp16 mma.sync, cp.async 2-stage K/V ring.
// CTA = 64 queries x (h, b), 4 warps (128 threads, 3 CTAs/SM).
// smem (half, stride 72): Qf[64*72] | 2 stages x {Kf, Vf}[64*72] | Mk[2][64] f32
// ---------------------------------------------------------------------------
#define AT_QF 0
#define AT_STG(s) (64 * 72 + (s) * (2 * 64 * 72))
#define AT_KF(s) (AT_STG(s))
#define AT_VF(s) (AT_STG(s) + 64 * 72)
#define AT_MK    (64 * 72 + 4 * 64 * 72)
#define AT_SMEM_BYTES ((64 * 72 + 4 * 64 * 72) * 2 + 2 * 64 * 4)  // 46592

__device__ __forceinline__ void at_issue(uint32_t sb, int s, int kb,
    const __half* __restrict__ Kf, const __half* __restrict__ Vf, int tid)
{
#pragma unroll
    for (int i = 0; i < 4; i++) {                  // 64 rows x 8 chunks
        const int slot = i * 128 + tid;
        const int row = slot >> 3;
        const int c   = (slot & 7) * 8;
        const size_t go = (size_t)(kb + row) * DHD + c;
        const uint32_t so = row * 72 + c;
        CP_ASYNC16(sb + (AT_KF(s) + so) * 2, Kf + go);
        CP_ASYNC16(sb + (AT_VF(s) + so) * 2, Vf + go);
    }
}

__global__ __launch_bounds__(128, 3)
void attn_mma_kernel(const int* __restrict__ mask, float* __restrict__ out)
{
    extern __shared__ __half smh[];
    float* Mkf = (float*)(smh + AT_MK);

    const int tid = threadIdx.x;
    const int l   = tid & 31;
    const int w   = tid >> 5;
    const int qt  = blockIdx.x;
    const int h   = blockIdx.y;
    const int b   = blockIdx.z;

    const size_t headoff = (size_t)((b * NH + h) * SEQ) * DHD;
    const __half* __restrict__ Qf = g_qf + headoff + (size_t)qt * 64 * DHD;
    const __half* __restrict__ Kf = g_kf + headoff;
    const __half* __restrict__ Vf = g_vf + headoff;
    const uint32_t sb = smem_u32(smh);

    // Preload: Q tile + first K/V tile + first mask slice, one cp.async group.
#pragma unroll
    for (int i = 0; i < 4; i++) {                  // Q: 64 rows x 8 chunks
        const int slot = i * 128 + tid;
        const int row = slot >> 3;
        const int c   = (slot & 7) * 8;
        CP_ASYNC16(sb + (AT_QF + row * 72 + c) * 2, Qf + (size_t)row * DHD + c);
    }
    at_issue(sb, 0, 0, Kf, Vf, tid);
    if (tid < 64)
        Mkf[tid] = -10000.0f * (1.0f - (float)mask[b * SEQ + tid]);
    CP_COMMIT();
    CP_WAIT0();
    __syncthreads();

    // Lift this warp's Q fragments into registers (persistent).
    uint32_t qf[4][4];
#pragma unroll
    for (int ks = 0; ks < 4; ks++) {
        const uint32_t off = (uint32_t)(w * 16 + (l & 15)) * 72 + ks * 16 + (l >> 4) * 8;
        ldsm_x4(sb + (AT_QF + off) * 2, qf[ks]);
    }

    float of[8][4] = {};
    float mrun[2] = {-1e30f, -1e30f};
    float lrun[2] = {0.0f, 0.0f};

    for (int t = 0; t < SEQ / 64; t++) {
        const int s = t & 1;
        if (t > 0) {
            CP_WAIT0();
            __syncthreads();
        }
        if (t + 1 < SEQ / 64) {
            at_issue(sb, s ^ 1, (t + 1) * 64, Kf, Vf, tid);
            if (tid < 64)
                Mkf[(s ^ 1) * 64 + tid] =
                    -10000.0f * (1.0f - (float)mask[b * SEQ + (t + 1) * 64 + tid]);
            CP_COMMIT();
        }

        // ---- S = Q K^T (m16 x n64, k=64, single fp16 MMA) ----
        float sf[8][4] = {};
#pragma unroll
        for (int ks = 0; ks < 4; ks++) {
            uint32_t bh[8][2];
#pragma unroll
            for (int nh = 0; nh < 4; nh++) {
                const uint32_t rowB = nh * 16 + (l & 7) + (l >> 4) * 8;
                const uint32_t kB   = ks * 16 + ((l >> 3) & 1) * 8;
                uint32_t q[4];
                ldsm_x4(sb + (AT_KF(s) + rowB * 72 + kB) * 2, q);
                bh[nh * 2][0] = q[0]; bh[nh * 2][1] = q[1];
                bh[nh * 2 + 1][0] = q[2]; bh[nh * 2 + 1][1] = q[3];
            }
#pragma unroll
            for (int nf = 0; nf < 8; nf++)
                mma16816h(sf[nf], qf[ks], bh[nf]);
        }

        // ---- online softmax (rows in 4-lane groups) ----
        float mk0[8], mk1[8];
#pragma unroll
        for (int nf = 0; nf < 8; nf++) {
            const float2 m2 = *(const float2*)&Mkf[s * 64 + nf * 8 + (l & 3) * 2];
            mk0[nf] = m2.x; mk1[nf] = m2.y;
        }
#pragma unroll
        for (int i = 0; i < 2; i++) {
            float mx = -1e30f;
#pragma unroll
            for (int nf = 0; nf < 8; nf++) {
                sf[nf][i * 2]     = sf[nf][i * 2]     * 0.125f + mk0[nf];
                sf[nf][i * 2 + 1] = sf[nf][i * 2 + 1] * 0.125f + mk1[nf];
                mx = fmaxf(mx, fmaxf(sf[nf][i * 2], sf[nf][i * 2 + 1]));
            }
            mx = fmaxf(mx, __shfl_xor_sync(0xffffffffu, mx, 1));
            mx = fmaxf(mx, __shfl_xor_sync(0xffffffffu, mx, 2));
            const float mnew = fmaxf(mrun[i], mx);
            const float fac  = __expf(mrun[i] - mnew);
            mrun[i] = mnew;
            float rs = 0.0f;
#pragma unroll
            for (int nf = 0; nf < 8; nf++) {
                const float p0 = __expf(sf[nf][i * 2]     - mnew);
                const float p1 = __expf(sf[nf][i * 2 + 1] - mnew);
                sf[nf][i * 2] = p0; sf[nf][i * 2 + 1] = p1;
                rs += p0 + p1;
            }
            rs += __shfl_xor_sync(0xffffffffu, rs, 1);
            rs += __shfl_xor_sync(0xffffffffu, rs, 2);
            lrun[i] = lrun[i] * fac + rs;
#pragma unroll
            for (int nj = 0; nj < 8; nj++) {
                of[nj][i * 2] *= fac; of[nj][i * 2 + 1] *= fac;
            }
        }

        // ---- repack P into fp16 A-frags ----
        uint32_t ph[4][4];
#pragma unroll
        for (int ks = 0; ks < 4; ks++) {
#pragma unroll
            for (int part = 0; part < 4; part++) {
                const int nf = ks * 2 + (part >> 1);
                const int ri = part & 1;
                ph[ks][part] = pack_h2(sf[nf][ri * 2], sf[nf][ri * 2 + 1]);
            }
        }

        // ---- O += P V (V via ldmatrix.trans, single fp16 MMA) ----
#pragma unroll
        for (int ks = 0; ks < 4; ks++) {
            uint32_t vh[8][2];
#pragma unroll
            for (int njp = 0; njp < 4; njp++) {
                const uint32_t rowV = ks * 16 + (l & 15);
                const uint32_t colV = (uint32_t)(njp * 2 + (l >> 4)) * 8;
                uint32_t q[4];
                ldsm_x4_t(sb + (AT_VF(s) + rowV * 72 + colV) * 2, q);
                vh[njp * 2][0] = q[0]; vh[njp * 2][1] = q[1];
                vh[njp * 2 + 1][0] = q[2]; vh[njp * 2 + 1][1] = q[3];
            }
#pragma unroll
            for (int nj = 0; nj < 8; nj++)
                mma16816h(of[nj], ph[ks], vh[nj]);
        }
    }

    // ---- epilogue: O / l -> out[b][s][h*64+dh] ----
#pragma unroll
    for (int i = 0; i < 2; i++) {
        const float inv = 1.0f / lrun[i];
        const int row = qt * 64 + w * 16 + (l >> 2) + i * 8;
        const size_t ob = ((size_t)(b * SEQ + row)) * DIM + h * DHD;
#pragma unroll
        for (int nj = 0; nj < 8; nj++) {
            const int dcol = nj * 8 + (l & 3) * 2;
            float2 o;
            o.x = of[nj][i * 2]     * inv;
            o.y = of[nj][i * 2 + 1] * inv;
            *(float2*)&out[ob + dcol] = o;
        }
    }
}

// ---------------------------------------------------------------------------
// Launch
// ---------------------------------------------------------------------------
extern "C" void kernel_launch(void* const* d_in, const int* in_sizes, int n_in,
                              void* d_out, int out_size)
{
    const float* x    = (const float*)d_in[0];
    const int*   mask = (const int*)  d_in[1];
    const float* Wq   = (const float*)d_in[2];
    const float* bq   = (const float*)d_in[3];
    const float* Wk   = (const float*)d_in[4];
    const float* bk   = (const float*)d_in[5];
    const float* Wv   = (const float*)d_in[6];
    const float* bv   = (const float*)d_in[7];
    float* out = (float*)d_out;

    cvt_x_kernel<<<MTOT * DIM / 4 / 256, 256>>>(x);

    dim3 gw(DIM / 32, DIM / 32, 3);
    cvt_w_kernel<<<gw, dim3(32, 8)>>>(Wq, Wk, Wv);

    cudaFuncSetAttribute(qkv_mma_kernel,
                         cudaFuncAttributeMaxDynamicSharedMemorySize, PJ_SMEM_BYTES);
    dim3 g1(DIM / 64, MTOT / 128, 3);
    qkv_mma_kernel<<<g1, 256, PJ_SMEM_BYTES>>>(bq, bk, bv);

    cudaFuncSetAttribute(attn_mma_kernel,
                         cudaFuncAttributeMaxDynamicSharedMemorySize, AT_SMEM_BYTES);
    dim3 g2(SEQ / 64, NH, BD);
    attn_mma_kernel<<<g2, 128, AT_SMEM_BYTES>>>(mask, out);
}